// round 16
// baseline (speedup 1.0000x reference)
#include <cuda_runtime.h>
#include <cuda_bf16.h>
#include <cstdint>

// GroupEmbedding: out[b,g,d] = sum_f x[b, group_idx[g,f]] * W[g,f,d] + bias[g,d]
// zeroed where masked_group_idx[b] == g.
// B=8192, NF=128, G=16, F=8, D=512. 256 MB output.
//
// R15 showed: FFMA2 halved issue (45.8->32.4%) but time flat -> NOT issue-bound.
// Nothing saturated + 32 warps/SM resident -> LATENCY-bound at low occupancy.
// R16: one thread per float2 column (W regs 32->16), 256 thr/block, 6 blocks/SM
//      = 48 warps/SM (+50% residency, +50% store streams). Persistent 880-block
//      grid (16 g x 55 <= 148*6=888 slots). Keep FFMA2 + (v,v) shared pairs.

#define B_TOTAL  8192
#define NF_      128
#define G_       16
#define F_       8
#define D_       512
#define D2_      (D_ / 2)            // 256 float2 per (b,g) -> one per thread
#define CHUNK    16                  // rows per chunk
#define NCHUNKS  (B_TOTAL / CHUNK)   // 512 chunks per group
#define JSTRIDE  55                  // blocks per group: 16*55 = 880 <= 888 slots
#define NTHREADS 256                 // one thread per d2 column

typedef unsigned long long ull;

#define FMA_F32X2(d, a, b, c) \
    asm("fma.rn.f32x2 %0, %1, %2, %3;" : "=l"(d) : "l"(a), "l"(b), "l"(c))

__global__ __launch_bounds__(NTHREADS, 6)
void group_embedding_kernel(const float* __restrict__ x,
                            const float* __restrict__ W,
                            const float* __restrict__ bias,
                            const int*   __restrict__ gidx_raw,   // int32 view; may be int64
                            const int*   __restrict__ mgi_raw,    // int32 view; may be int64
                            float*       __restrict__ out)
{
    const int bx = blockIdx.x;
    const int g  = bx & 15;             // group: constant for this block
    const int j  = bx >> 4;             // 0..54, chunk stripe
    const int t  = threadIdx.x;         // 0..255 -> d2 column

    __shared__ ull xs2[CHUNK][F_];      // (v,v) duplicated pairs; broadcast-read
    __shared__ int msk[CHUNK];
    __shared__ int cols[F_];
    __shared__ int flags;               // bit0: gidx is int32; bit1: mgi is int32

    // --- dtype detection: int64 LE values (<128) have all-zero odd 32-bit words ---
    if (t < 32) {
        int pg = gidx_raw[2 * t + 1];
        int pm = mgi_raw[2 * t + 1];
        int gi32 = __any_sync(0xffffffffu, pg != 0);
        int mi32 = __any_sync(0xffffffffu, pm != 0);
        if (t == 0) flags = (gi32 ? 1 : 0) | (mi32 ? 2 : 0);
    }
    __syncthreads();
    const bool gidx_i32 = (flags & 1) != 0;
    const bool mgi_i32  = (flags & 2) != 0;

    if (t < F_) {
        int idx = g * F_ + t;
        cols[t] = gidx_i32 ? gidx_raw[idx] : gidx_raw[2 * idx];
    }
    __syncthreads();

    // --- W column (8 float2 pairs = 16 regs) + bias; reused for all chunks ---
    const ull* __restrict__ W2 = (const ull*)W;    // W row = 512 f32 = 256 ulls
    ull w[F_];
#pragma unroll
    for (int f = 0; f < F_; f++)
        w[f] = W2[(g * F_ + f) * D2_ + t];
    const ull bb = ((const ull*)bias)[g * D2_ + t];

    const int ROWSTRIDE = G_ * D2_;     // float2 units between consecutive b rows
    float2* __restrict__ out2 = (float2*)out;

    // gather role fixed per thread (only t<128 load x; t<16 load mask)
    const int gr = t >> 3, gf = t & 7;
    const int gcol = cols[gf];

    // --- persistent loop over this block's chunks (~9-10 per block) ---
    for (int cb = j; cb < NCHUNKS; cb += JSTRIDE) {
        const int b0 = cb * CHUNK;

        if (t < CHUNK * F_) {
            float v = x[(b0 + gr) * NF_ + gcol];
            float2 vv = make_float2(v, v);
            xs2[gr][gf] = *(const ull*)&vv;
        }
        if (t < CHUNK)
            msk[t] = mgi_i32 ? mgi_raw[b0 + t] : mgi_raw[2 * (b0 + t)];
        __syncthreads();

        float2* __restrict__ p = out2 + ((size_t)b0 * G_ + (size_t)g) * D2_ + t;
#pragma unroll
        for (int r = 0; r < CHUNK; r++) {
            ull a = bb;
#pragma unroll
            for (int f = 0; f < F_; f++) {
                const ull xv = xs2[r][f];          // LDS.64 broadcast: (x, x)
                FMA_F32X2(a, xv, w[f], a);         // 2 MACs / instruction
            }
            if (msk[r] == g) a = 0ull;
            *(ull*)p = a;                          // plain coalesced STG.64
            p += ROWSTRIDE;
        }
        __syncthreads();                           // protect xs2/msk before next gather
    }
}

extern "C" void kernel_launch(void* const* d_in, const int* in_sizes, int n_in,
                              void* d_out, int out_size)
{
    const float* x    = (const float*)d_in[0];
    const float* W    = (const float*)d_in[1];
    const float* bias = (const float*)d_in[2];
    const int*   gidx = (const int*)d_in[3];
    const int*   mgi  = (const int*)d_in[4];
    float*       out  = (float*)d_out;

    group_embedding_kernel<<<G_ * JSTRIDE, NTHREADS>>>(x, W, bias, gidx, mgi, out);
}

// round 17
// speedup vs baseline: 1.1388x; 1.1388x over previous
#include <cuda_runtime.h>
#include <cuda_bf16.h>
#include <cstdint>

// GroupEmbedding: out[b,g,d] = sum_f x[b, group_idx[g,f]] * W[g,f,d] + bias[g,d]
// zeroed where masked_group_idx[b] == g.
// B=8192, NF=128, G=16, F=8, D=512. 256 MB output (HBM-write dominated).
//
// Evidence log: STG.128 variants all ~44.5-46.8us @ 4.5-4.8 TB/s, nothing >61% busy.
//   R6 (__stcs) and R16 (STG.64, high occ) both regressed with L1tex>75%.
// R17: discriminate "HBM write wall" vs "warp latency chain": R3's exact fastest
//   skeleton (grid 2048, 128 thr, float4, plain STG.128, occ ~41%) with the
//   dependency chain shortened: FFMA2 + split even/odd accumulators (chain 8->4)
//   + 2 rows/iter ILP. Store path and occupancy deliberately untouched.

#define B_TOTAL  8192
#define NF_      128
#define G_       16
#define F_       8
#define D_       512
#define D4_      (D_ / 4)       // 128 float4 per (b,g)
#define BROWS    64             // rows per block (R3 config)
#define NTHREADS 128            // one thread per d4 column

typedef unsigned long long ull;

#define FMA_F32X2(d, a, b, c) \
    asm("fma.rn.f32x2 %0, %1, %2, %3;" : "=l"(d) : "l"(a), "l"(b), "l"(c))
#define ADD_F32X2_(d, a, b) \
    asm("add.rn.f32x2 %0, %1, %2;" : "=l"(d) : "l"(a), "l"(b))

__global__ __launch_bounds__(NTHREADS, 8)
void group_embedding_kernel(const float* __restrict__ x,
                            const float* __restrict__ W,
                            const float* __restrict__ bias,
                            const int*   __restrict__ gidx_raw,   // int32 view; may be int64
                            const int*   __restrict__ mgi_raw,    // int32 view; may be int64
                            float*       __restrict__ out)
{
    const int g  = blockIdx.x;          // 0..15
    const int b0 = blockIdx.y * BROWS;  // row tile base
    const int t  = threadIdx.x;         // 0..127 -> d4 column

    __shared__ ull xs2[BROWS][F_];      // (v,v) duplicated pairs; broadcast-read
    __shared__ int msk[BROWS];
    __shared__ int cols[F_];
    __shared__ int flags;               // bit0: gidx is int32; bit1: mgi is int32

    // --- dtype detection: int64 LE values (<128) have all-zero odd 32-bit words ---
    if (t < 32) {
        int pg = gidx_raw[2 * t + 1];
        int pm = mgi_raw[2 * t + 1];
        int gi32 = __any_sync(0xffffffffu, pg != 0);
        int mi32 = __any_sync(0xffffffffu, pm != 0);
        if (t == 0) flags = (gi32 ? 1 : 0) | (mi32 ? 2 : 0);
    }
    __syncthreads();
    const bool gidx_i32 = (flags & 1) != 0;
    const bool mgi_i32  = (flags & 2) != 0;

    if (t < F_) {
        int idx = g * F_ + t;
        cols[t] = gidx_i32 ? gidx_raw[idx] : gidx_raw[2 * idx];
    }
    __syncthreads();

    // --- W column (8 float4 -> 16 b64 halves) + bias regs; reused for 64 rows ---
    const float4* __restrict__ W4 = (const float4*)W;
    ull w01[F_], w23[F_];
#pragma unroll
    for (int f = 0; f < F_; f++) {
        float4 wf = W4[(g * F_ + f) * D4_ + t];
        w01[f] = ((const ull*)&wf)[0];
        w23[f] = ((const ull*)&wf)[1];
    }
    float4 bb = ((const float4*)bias)[g * D4_ + t];
    const ull bb01 = ((const ull*)&bb)[0];
    const ull bb23 = ((const ull*)&bb)[1];

    // --- gather x tile as duplicated (v,v) pairs + masks ---
    for (int i = t; i < BROWS * F_; i += NTHREADS) {
        int r = i >> 3, f = i & 7;
        float v = x[(b0 + r) * NF_ + cols[f]];
        float2 vv = make_float2(v, v);
        xs2[r][f] = *(const ull*)&vv;
    }
    {
        int b = b0 + (t & 63);
        if (t < BROWS) msk[t] = mgi_i32 ? mgi_raw[b] : mgi_raw[2 * b];
    }
    __syncthreads();

    // --- mainloop: 2 rows/iter, split even/odd accumulators (chain depth 4) ---
    const int ROWSTRIDE = G_ * D4_;     // float4 units between consecutive b rows
    float4* __restrict__ p =
        (float4*)out + ((size_t)b0 * G_ + (size_t)g) * D4_ + t;

#pragma unroll 4
    for (int r = 0; r < BROWS; r += 2) {
        // row r: even-f chain seeds with bias, odd-f chain seeds with first product
        ull Ae01 = bb01, Ae23 = bb23, Ao01, Ao23;
        ull Be01 = bb01, Be23 = bb23, Bo01, Bo23;
        {
            const ull x0a = xs2[r][1],     x0b = xs2[r + 1][1];
            asm("mul.rn.f32x2 %0, %1, %2;" : "=l"(Ao01) : "l"(x0a), "l"(w01[1]));
            asm("mul.rn.f32x2 %0, %1, %2;" : "=l"(Ao23) : "l"(x0a), "l"(w23[1]));
            asm("mul.rn.f32x2 %0, %1, %2;" : "=l"(Bo01) : "l"(x0b), "l"(w01[1]));
            asm("mul.rn.f32x2 %0, %1, %2;" : "=l"(Bo23) : "l"(x0b), "l"(w23[1]));
        }
#pragma unroll
        for (int f = 0; f < F_; f += 2) {
            const ull xeA = xs2[r][f],     xeB = xs2[r + 1][f];
            FMA_F32X2(Ae01, xeA, w01[f], Ae01);
            FMA_F32X2(Ae23, xeA, w23[f], Ae23);
            FMA_F32X2(Be01, xeB, w01[f], Be01);
            FMA_F32X2(Be23, xeB, w23[f], Be23);
            if (f + 3 < F_ + 1 && f > 0) { /* odd handled below */ }
        }
#pragma unroll
        for (int f = 3; f < F_; f += 2) {
            const ull xoA = xs2[r][f],     xoB = xs2[r + 1][f];
            FMA_F32X2(Ao01, xoA, w01[f], Ao01);
            FMA_F32X2(Ao23, xoA, w23[f], Ao23);
            FMA_F32X2(Bo01, xoB, w01[f], Bo01);
            FMA_F32X2(Bo23, xoB, w23[f], Bo23);
        }
        ull a01, a23, b01, b23;
        ADD_F32X2_(a01, Ae01, Ao01);
        ADD_F32X2_(a23, Ae23, Ao23);
        ADD_F32X2_(b01, Be01, Bo01);
        ADD_F32X2_(b23, Be23, Bo23);

        if (msk[r]     == g) { a01 = 0ull; a23 = 0ull; }
        if (msk[r + 1] == g) { b01 = 0ull; b23 = 0ull; }

        float4 o0, o1;
        ((ull*)&o0)[0] = a01; ((ull*)&o0)[1] = a23;
        ((ull*)&o1)[0] = b01; ((ull*)&o1)[1] = b23;
        p[0]         = o0;              // plain coalesced STG.128 (proven path)
        p[ROWSTRIDE] = o1;
        p += 2 * ROWSTRIDE;
    }
}

extern "C" void kernel_launch(void* const* d_in, const int* in_sizes, int n_in,
                              void* d_out, int out_size)
{
    const float* x    = (const float*)d_in[0];
    const float* W    = (const float*)d_in[1];
    const float* bias = (const float*)d_in[2];
    const int*   gidx = (const int*)d_in[3];
    const int*   mgi  = (const int*)d_in[4];
    float*       out  = (float*)d_out;

    dim3 grid(G_, B_TOTAL / BROWS);   // 16 x 128 = 2048 blocks (R3's fastest grid)
    group_embedding_kernel<<<grid, NTHREADS>>>(x, W, bias, gidx, mgi, out);
}